// round 1
// baseline (speedup 1.0000x reference)
#include <cuda_runtime.h>

// ---------------------------------------------------------------------------
// Fused MoE (DeepSeek-V2 style), grouped-GEMM formulation.
//   T=1024 tokens, H=2048 hidden, F=1408 ffn, E=32 experts, K=6 topk.
//   out[t,:] = sum_k w[t,k] * down_w[e] @ ( silu(gate) * up ),
//     [gate|up] = gate_up_w[e] @ x[t],  e = topk_ids[t,k]
// Pipeline (all device-side, graph-capturable, allocation-free):
//   zero_out -> setup(dtype detect + zero counters) -> hist -> scan/tiles
//   -> fill -> GEMM1 (gate_up) -> SwiGLU -> GEMM2 (down) + weighted scatter
// ---------------------------------------------------------------------------

#define T_TOK 1024
#define HID   2048
#define FF    1408
#define NEXP  32
#define TOPK  6
#define NA    (T_TOK * TOPK)   // 6144 assignments
#define GUN   (2 * FF)         // 2816
#define MAXTILES 160

#define BM 64
#define BN 128
#define BK 16

// ---------------- scratch (static device globals; no allocations) ----------
__device__ int   d_count[NEXP];
__device__ int   d_fill[NEXP];
__device__ int   d_flag;                 // 1 => topk_ids is int32, 0 => int64
__device__ int   d_ntiles;
__device__ int   d_tileE[MAXTILES];
__device__ int   d_tileR0[MAXTILES];
__device__ int   d_tileRows[MAXTILES];
__device__ int   d_tok[NA];              // token index per sorted assignment
__device__ float d_wt[NA];               // routing weight per sorted assignment
__device__ float d_G[(long long)NA * GUN];   // gate_up results  (~69 MB)
__device__ float d_Hb[(long long)NA * FF];   // swiglu results   (~35 MB)

// ---------------- small kernels --------------------------------------------

__global__ void k_zero_out(float4* out) {
    out[blockIdx.x * blockDim.x + threadIdx.x] = make_float4(0.f, 0.f, 0.f, 0.f);
}

// Zero counters and detect topk_ids dtype.
// If int64 (little-endian, values in [0,32)): every odd int32 word is 0.
// If int32: odd words are ids, almost surely nonzero somewhere in 3072 probes.
// Scanning 3072 int32-pairs touches exactly 6144 int32s = the int32 buffer
// size, so no OOB in either case.
__global__ void k_setup(const int* __restrict__ ids32) {
    __shared__ int f;
    int tid = threadIdx.x;
    if (tid < NEXP) { d_count[tid] = 0; }
    if (tid == 0) f = 0;
    __syncthreads();
    int local = 0;
    for (int i = tid; i < NA / 2; i += blockDim.x)
        if (ids32[2 * i + 1] != 0) local = 1;
    if (local) f = 1;
    __syncthreads();
    if (tid == 0) d_flag = f;
}

__device__ __forceinline__ int get_id(const int* ids32, int i, int flag) {
    return flag ? ids32[i] : ids32[2 * i];
}

__global__ void k_hist(const int* __restrict__ ids32) {
    int i = blockIdx.x * blockDim.x + threadIdx.x;
    if (i >= NA) return;
    int e = get_id(ids32, i, d_flag);
    atomicAdd(&d_count[e], 1);
}

// Serial scan over 32 experts + build M-tile list (<= 96 + 32 = 128 tiles).
__global__ void k_scan() {
    int off = 0, nt = 0;
    for (int e = 0; e < NEXP; e++) {
        d_fill[e] = off;
        int c = d_count[e];
        for (int r = 0; r < c; r += BM) {
            d_tileE[nt]    = e;
            d_tileR0[nt]   = off + r;
            d_tileRows[nt] = (c - r < BM) ? (c - r) : BM;
            nt++;
        }
        off += c;
    }
    d_ntiles = nt;
}

__global__ void k_fill(const int* __restrict__ ids32,
                       const float* __restrict__ tw) {
    int i = blockIdx.x * blockDim.x + threadIdx.x;
    if (i >= NA) return;
    int e   = get_id(ids32, i, d_flag);
    int pos = atomicAdd(&d_fill[e], 1);
    d_tok[pos] = i / TOPK;
    d_wt[pos]  = tw[i];
}

// ---------------- GEMM1: G[rows, 2816] = X_gathered @ W1[e]^T --------------
// A: x rows gathered via d_tok (row-major, K=2048 contiguous)
// B: gate_up_weights[e] : [2816, 2048] row-major (K contiguous)
__global__ __launch_bounds__(256) void k_gemm1(const float* __restrict__ x,
                                               const float* __restrict__ w) {
    int ti = blockIdx.y;
    if (ti >= d_ntiles) return;
    int e = d_tileE[ti], row0 = d_tileR0[ti], rows = d_tileRows[ti];
    int n0 = blockIdx.x * BN;

    __shared__ float As[BK][BM + 4];
    __shared__ float Bs[BK][BN + 4];

    int tid = threadIdx.x;
    int kg = tid & 3;          // k-group (4 floats each)
    int lr = tid >> 2;         // 0..63 load row
    const float* aPtr = nullptr;
    if (lr < rows) aPtr = x + (long long)d_tok[row0 + lr] * HID + kg * 4;
    const float* bPtr = w + (long long)e * GUN * HID
                          + (long long)(n0 + lr) * HID + kg * 4;

    int tm = tid >> 4;         // 0..15 -> 4 rows
    int tn = tid & 15;         // 0..15 -> 8 cols
    float acc[4][8];
#pragma unroll
    for (int i = 0; i < 4; i++)
#pragma unroll
        for (int j = 0; j < 8; j++) acc[i][j] = 0.f;

    for (int k0 = 0; k0 < HID; k0 += BK) {
        float4 av = make_float4(0.f, 0.f, 0.f, 0.f);
        if (aPtr) av = *(const float4*)(aPtr + k0);
        float4 b0 = *(const float4*)(bPtr + k0);
        float4 b1 = *(const float4*)(bPtr + k0 + (long long)64 * HID);
        As[kg * 4 + 0][lr] = av.x; As[kg * 4 + 1][lr] = av.y;
        As[kg * 4 + 2][lr] = av.z; As[kg * 4 + 3][lr] = av.w;
        Bs[kg * 4 + 0][lr] = b0.x; Bs[kg * 4 + 1][lr] = b0.y;
        Bs[kg * 4 + 2][lr] = b0.z; Bs[kg * 4 + 3][lr] = b0.w;
        Bs[kg * 4 + 0][lr + 64] = b1.x; Bs[kg * 4 + 1][lr + 64] = b1.y;
        Bs[kg * 4 + 2][lr + 64] = b1.z; Bs[kg * 4 + 3][lr + 64] = b1.w;
        __syncthreads();
#pragma unroll
        for (int kk = 0; kk < BK; kk++) {
            float4 a = *(const float4*)&As[kk][tm * 4];
            float4 p = *(const float4*)&Bs[kk][tn * 8];
            float4 q = *(const float4*)&Bs[kk][tn * 8 + 4];
            float am[4] = {a.x, a.y, a.z, a.w};
            float bn[8] = {p.x, p.y, p.z, p.w, q.x, q.y, q.z, q.w};
#pragma unroll
            for (int i = 0; i < 4; i++)
#pragma unroll
                for (int j = 0; j < 8; j++) acc[i][j] += am[i] * bn[j];
        }
        __syncthreads();
    }
#pragma unroll
    for (int i = 0; i < 4; i++) {
        int m = tm * 4 + i;
        if (m < rows) {
            float* g = d_G + (long long)(row0 + m) * GUN + n0 + tn * 8;
#pragma unroll
            for (int j = 0; j < 8; j++) g[j] = acc[i][j];
        }
    }
}

// ---------------- SwiGLU: Hb = silu(gate) * up -----------------------------
__global__ void k_act() {
    const long long total = (long long)NA * FF;
    for (long long i = blockIdx.x * (long long)blockDim.x + threadIdx.x;
         i < total; i += (long long)gridDim.x * blockDim.x) {
        int p = (int)(i / FF), f = (int)(i % FF);
        float g = d_G[(long long)p * GUN + f];
        float u = d_G[(long long)p * GUN + FF + f];
        float s = 1.f / (1.f + expf(-g));
        d_Hb[i] = g * s * u;
    }
}

// ---------------- GEMM2: Y = Hb @ W2[e]^T, scatter w*Y into out ------------
// A: d_Hb rows (K=1408 contiguous);  B: down_weights[e] : [2048, 1408]
__global__ __launch_bounds__(256) void k_gemm2(const float* __restrict__ w,
                                               float* __restrict__ out) {
    int ti = blockIdx.y;
    if (ti >= d_ntiles) return;
    int e = d_tileE[ti], row0 = d_tileR0[ti], rows = d_tileRows[ti];
    int n0 = blockIdx.x * BN;

    __shared__ float As[BK][BM + 4];
    __shared__ float Bs[BK][BN + 4];

    int tid = threadIdx.x;
    int kg = tid & 3;
    int lr = tid >> 2;
    const float* aPtr = nullptr;
    if (lr < rows) aPtr = d_Hb + (long long)(row0 + lr) * FF + kg * 4;
    const float* bPtr = w + (long long)e * HID * FF
                          + (long long)(n0 + lr) * FF + kg * 4;

    int tm = tid >> 4;
    int tn = tid & 15;
    float acc[4][8];
#pragma unroll
    for (int i = 0; i < 4; i++)
#pragma unroll
        for (int j = 0; j < 8; j++) acc[i][j] = 0.f;

    for (int k0 = 0; k0 < FF; k0 += BK) {
        float4 av = make_float4(0.f, 0.f, 0.f, 0.f);
        if (aPtr) av = *(const float4*)(aPtr + k0);
        float4 b0 = *(const float4*)(bPtr + k0);
        float4 b1 = *(const float4*)(bPtr + k0 + (long long)64 * FF);
        As[kg * 4 + 0][lr] = av.x; As[kg * 4 + 1][lr] = av.y;
        As[kg * 4 + 2][lr] = av.z; As[kg * 4 + 3][lr] = av.w;
        Bs[kg * 4 + 0][lr] = b0.x; Bs[kg * 4 + 1][lr] = b0.y;
        Bs[kg * 4 + 2][lr] = b0.z; Bs[kg * 4 + 3][lr] = b0.w;
        Bs[kg * 4 + 0][lr + 64] = b1.x; Bs[kg * 4 + 1][lr + 64] = b1.y;
        Bs[kg * 4 + 2][lr + 64] = b1.z; Bs[kg * 4 + 3][lr + 64] = b1.w;
        __syncthreads();
#pragma unroll
        for (int kk = 0; kk < BK; kk++) {
            float4 a = *(const float4*)&As[kk][tm * 4];
            float4 p = *(const float4*)&Bs[kk][tn * 8];
            float4 q = *(const float4*)&Bs[kk][tn * 8 + 4];
            float am[4] = {a.x, a.y, a.z, a.w};
            float bn[8] = {p.x, p.y, p.z, p.w, q.x, q.y, q.z, q.w};
#pragma unroll
            for (int i = 0; i < 4; i++)
#pragma unroll
                for (int j = 0; j < 8; j++) acc[i][j] += am[i] * bn[j];
        }
        __syncthreads();
    }
#pragma unroll
    for (int i = 0; i < 4; i++) {
        int m = tm * 4 + i;
        if (m < rows) {
            int idx = row0 + m;
            int t = d_tok[idx];
            float wv = d_wt[idx];
            float* o = out + (long long)t * HID + n0 + tn * 8;
#pragma unroll
            for (int j = 0; j < 8; j++) atomicAdd(&o[j], wv * acc[i][j]);
        }
    }
}

// ---------------- launch ---------------------------------------------------

extern "C" void kernel_launch(void* const* d_in, const int* in_sizes, int n_in,
                              void* d_out, int out_size) {
    const float* x   = (const float*)d_in[0];
    const float* w1  = (const float*)d_in[1];
    const float* w2  = (const float*)d_in[2];
    const float* tw  = (const float*)d_in[3];
    const int*   ids = (const int*)d_in[4];   // int32 or int64 (auto-detected)
    float* out = (float*)d_out;

    k_zero_out<<<1024, 512>>>((float4*)out);              // 1024*2048 floats
    k_setup<<<1, 256>>>(ids);
    k_hist<<<(NA + 255) / 256, 256>>>(ids);
    k_scan<<<1, 1>>>();
    k_fill<<<(NA + 255) / 256, 256>>>(ids, tw);
    k_gemm1<<<dim3(GUN / BN, 128), 256>>>(x, w1);         // 22 x <=128 tiles
    k_act<<<4096, 256>>>();
    k_gemm2<<<dim3(HID / BN, 128), 256>>>(w2, out);       // 16 x <=128 tiles
}

// round 3
// speedup vs baseline: 3.7457x; 3.7457x over previous
#include <cuda_runtime.h>

// ---------------------------------------------------------------------------
// Fused MoE via grouped tf32 mma.sync GEMMs (legacy tensor path; tcgen05 is
// unavailable because the harness compiles at virtual target compute_103).
//   T=1024, H=2048, F=1408, E=32, K=6.
// Pipeline: setup -> hist -> scan -> fill -> GEMM1 -> swiglu -> GEMM2
//           -> combine (inverse-permutation weighted gather).
// ---------------------------------------------------------------------------

#define T_TOK 1024
#define HID   2048
#define FF    1408
#define NEXP  32
#define TOPK  6
#define NA    (T_TOK * TOPK)    // 6144
#define GUN   (2 * FF)          // 2816

typedef unsigned int u32;

// ---------------- device scratch -------------------------------------------
__device__ int   d_count[NEXP];
__device__ int   d_off[NEXP];
__device__ int   d_fill[NEXP];
__device__ int   d_flag;                       // 1 => ids are int32
__device__ int   d_tok[NA];
__device__ int   d_inv[NA];                    // assignment -> sorted pos
__device__ float d_G [(size_t)NA * GUN];       // ~69 MB
__device__ float d_Hb[(size_t)NA * FF];        // ~35 MB
__device__ float d_Y [(size_t)NA * HID];       // ~50 MB

// ---------------- PTX helpers ----------------------------------------------
__device__ __forceinline__ u32 smem_u32(const void* p) {
    u32 a;
    asm("{ .reg .u64 t; cvta.to.shared.u64 t, %1; cvt.u32.u64 %0, t; }"
        : "=r"(a) : "l"(p));
    return a;
}
__device__ __forceinline__ u32 f2tf(float f) {      // fp32 -> tf32 RN (unbiased)
    u32 r;
    asm("cvt.rna.tf32.f32 %0, %1;" : "=r"(r) : "f"(f));
    return r;
}
#define CP16(dst, src, sz) \
    asm volatile("cp.async.ca.shared.global [%0], [%1], 16, %2;" \
                 :: "r"(dst), "l"(src), "r"(sz))
#define CP_COMMIT() asm volatile("cp.async.commit_group;" ::: "memory")
#define CP_WAIT(n)  asm volatile("cp.async.wait_group %0;" :: "n"(n) : "memory")

__device__ __forceinline__ void mma8(float* d, const u32* a, const u32* b) {
    asm volatile(
        "mma.sync.aligned.m16n8k8.row.col.f32.tf32.tf32.f32 "
        "{%0,%1,%2,%3}, {%4,%5,%6,%7}, {%8,%9}, {%0,%1,%2,%3};"
        : "+f"(d[0]), "+f"(d[1]), "+f"(d[2]), "+f"(d[3])
        : "r"(a[0]), "r"(a[1]), "r"(a[2]), "r"(a[3]), "r"(b[0]), "r"(b[1]));
}

// ---------------- routing prep ---------------------------------------------
__global__ void k_setup(const int* __restrict__ ids32) {
    __shared__ int f;
    int tid = threadIdx.x;
    if (tid < NEXP) d_count[tid] = 0;
    if (tid == 0) f = 0;
    __syncthreads();
    int local = 0;
    for (int i = tid; i < NA / 2; i += blockDim.x)
        if (ids32[2 * i + 1] != 0) local = 1;
    if (local) f = 1;
    __syncthreads();
    if (tid == 0) d_flag = f;
}
__device__ __forceinline__ int get_id(const int* ids32, int i, int flag) {
    return flag ? ids32[i] : ids32[2 * i];
}
__global__ void k_hist(const int* __restrict__ ids32) {
    int i = blockIdx.x * blockDim.x + threadIdx.x;
    if (i >= NA) return;
    atomicAdd(&d_count[get_id(ids32, i, d_flag)], 1);
}
__global__ void k_scan() {
    int off = 0;
    for (int e = 0; e < NEXP; e++) {
        d_off[e] = off; d_fill[e] = off; off += d_count[e];
    }
}
__global__ void k_fill(const int* __restrict__ ids32) {
    int i = blockIdx.x * blockDim.x + threadIdx.x;
    if (i >= NA) return;
    int e = get_id(ids32, i, d_flag);
    int pos = atomicAdd(&d_fill[e], 1);
    d_tok[pos] = i / TOPK;
    d_inv[i] = pos;
}

// ---------------- grouped tf32 GEMM ----------------------------------------
// BM=256 rows (whole expert usually), BN=128 cols, BK=16, 512 threads.
// 16 warps, warp tile 64x32 (4x4 of m16n8k8). 2-stage cp.async pipeline.
// Shared (bytes): A: 2 x 256x20 floats = 40960; B: 2 x 128x20 = 20480. 61440 total.
// OUTSEL 0: C=d_G (ldc GUN), B=gate_up[e] [GUN x K]. A = x gathered by d_tok.
// OUTSEL 1: C=d_Y (ldc HID), B=down[e]    [HID x K]. A = d_Hb rows.
#define ASTG 20480u
#define BSTG 10240u
#define BOFF 40960u

template<int KDIM, int GATHER, int OUTSEL>
__global__ __launch_bounds__(512, 1) void k_gemm(const float* __restrict__ Ain,
                                                 const float* __restrict__ Bw) {
    constexpr int NIT = KDIM / 16;
    extern __shared__ char smem[];
    const int e = blockIdx.y;
    const int cnt = d_count[e];
    if (cnt == 0) return;
    const int row0e = d_off[e];
    const int n0 = blockIdx.x * 128;
    const long long bStride = (OUTSEL == 0) ? (long long)GUN * HID
                                            : (long long)HID * FF;
    float* Cb = (OUTSEL == 0) ? d_G : d_Y;
    const int ldc = (OUTSEL == 0) ? GUN : HID;
    const float* A = GATHER ? Ain : d_Hb;

    const int tid = threadIdx.x;
    const int wid = tid >> 5, lane = tid & 31;
    const int r4 = lane >> 2, c4 = lane & 3;
    const int warpM = (wid & 3) * 64;
    const int warpN = (wid >> 2) * 32;
    const u32 sb = smem_u32(smem);

    // loader geometry: lrow 0..127, lc = 16B chunk 0..3
    const int lrow = tid >> 2;
    const int lc   = tid & 3;
    const float* bSrc = Bw + (long long)e * bStride
                           + (long long)(n0 + lrow) * KDIM + lc * 4;
    const u32 bDst = sb + BOFF + (u32)lrow * 80u + (u32)lc * 16u;

    for (int m0 = 0; m0 < cnt; m0 += 256) {
        // per-tile A row sources (2 rows per thread: lrow, lrow+128)
        const float* aSrc[2]; u32 aSz[2]; u32 aDst[2];
#pragma unroll
        for (int j = 0; j < 2; j++) {
            int r = lrow + j * 128;
            int valid = (m0 + r) < cnt;
            long long src = 0;
            if (valid)
                src = GATHER ? (long long)d_tok[row0e + m0 + r]
                             : (long long)(row0e + m0 + r);
            aSrc[j] = A + src * KDIM + lc * 4;
            aSz[j]  = valid ? 16u : 0u;
            aDst[j] = sb + (u32)r * 80u + (u32)lc * 16u;
        }

        float acc[4][4][4];
#pragma unroll
        for (int mt = 0; mt < 4; mt++)
#pragma unroll
            for (int nt = 0; nt < 4; nt++)
#pragma unroll
                for (int q = 0; q < 4; q++) acc[mt][nt][q] = 0.f;

        // prologue: stage 0
        CP16(aDst[0], aSrc[0], aSz[0]);
        CP16(aDst[1], aSrc[1], aSz[1]);
        CP16(bDst, bSrc, 16u);
        CP_COMMIT();

        for (int it = 0; it < NIT; it++) {
            const int buf = it & 1;
            if (it + 1 < NIT) {
                const int nb = (it + 1) & 1;
                const int k0 = (it + 1) * 16;
                CP16(aDst[0] + nb * ASTG, aSrc[0] + k0, aSz[0]);
                CP16(aDst[1] + nb * ASTG, aSrc[1] + k0, aSz[1]);
                CP16(bDst + nb * BSTG, bSrc + k0, 16u);
                CP_COMMIT();
                CP_WAIT(1);
            } else {
                CP_WAIT(0);
            }
            __syncthreads();

            const float* Af = (const float*)(smem + buf * ASTG);
            const float* Bf = (const float*)(smem + BOFF + buf * BSTG);
#pragma unroll
            for (int ks = 0; ks < 2; ks++) {
                u32 a[4][4], b[4][2];
#pragma unroll
                for (int mt = 0; mt < 4; mt++) {
                    int mb = (warpM + mt * 16 + r4) * 20 + ks * 8 + c4;
                    a[mt][0] = f2tf(Af[mb]);
                    a[mt][1] = f2tf(Af[mb + 160]);
                    a[mt][2] = f2tf(Af[mb + 4]);
                    a[mt][3] = f2tf(Af[mb + 164]);
                }
#pragma unroll
                for (int nt = 0; nt < 4; nt++) {
                    int nb = (warpN + nt * 8 + r4) * 20 + ks * 8 + c4;
                    b[nt][0] = f2tf(Bf[nb]);
                    b[nt][1] = f2tf(Bf[nb + 4]);
                }
#pragma unroll
                for (int mt = 0; mt < 4; mt++)
#pragma unroll
                    for (int nt = 0; nt < 4; nt++)
                        mma8(acc[mt][nt], a[mt], b[nt]);
            }
            __syncthreads();
        }

        // epilogue
#pragma unroll
        for (int mt = 0; mt < 4; mt++) {
            int rloc = m0 + warpM + mt * 16 + r4;
#pragma unroll
            for (int nt = 0; nt < 4; nt++) {
                int col = n0 + warpN + nt * 8 + c4 * 2;
                if (rloc < cnt) {
                    float2 v = make_float2(acc[mt][nt][0], acc[mt][nt][1]);
                    *(float2*)&Cb[(long long)(row0e + rloc) * ldc + col] = v;
                }
                if (rloc + 8 < cnt) {
                    float2 v = make_float2(acc[mt][nt][2], acc[mt][nt][3]);
                    *(float2*)&Cb[(long long)(row0e + rloc + 8) * ldc + col] = v;
                }
            }
        }
        __syncthreads();   // before next m-tile's prologue reuses stage 0
    }
}

// ---------------- SwiGLU ----------------------------------------------------
__global__ void k_act() {
    const long long total = (long long)NA * FF;
    for (long long i = blockIdx.x * (long long)blockDim.x + threadIdx.x;
         i < total; i += (long long)gridDim.x * blockDim.x) {
        int p = (int)(i / FF), f = (int)(i % FF);
        float gv = d_G[(long long)p * GUN + f];
        float uv = d_G[(long long)p * GUN + FF + f];
        float s = 1.f / (1.f + __expf(-gv));
        d_Hb[i] = gv * s * uv;
    }
}

// ---------------- combine: out[t] = sum_k w[t,k] * Y[inv[t,k]] --------------
__global__ void k_combine(const float* __restrict__ tw, float* __restrict__ out) {
    int t = blockIdx.x;
    __shared__ int pos[TOPK];
    __shared__ float wv[TOPK];
    if (threadIdx.x < TOPK) {
        pos[threadIdx.x] = d_inv[t * TOPK + threadIdx.x];
        wv[threadIdx.x]  = tw[t * TOPK + threadIdx.x];
    }
    __syncthreads();
    for (int h = threadIdx.x * 4; h < HID; h += blockDim.x * 4) {
        float4 acc = make_float4(0.f, 0.f, 0.f, 0.f);
#pragma unroll
        for (int k = 0; k < TOPK; k++) {
            float4 v = *(const float4*)(d_Y + (size_t)pos[k] * HID + h);
            acc.x += wv[k] * v.x; acc.y += wv[k] * v.y;
            acc.z += wv[k] * v.z; acc.w += wv[k] * v.w;
        }
        *(float4*)(out + (size_t)t * HID + h) = acc;
    }
}

// ---------------- launch ----------------------------------------------------
extern "C" void kernel_launch(void* const* d_in, const int* in_sizes, int n_in,
                              void* d_out, int out_size) {
    const float* x   = (const float*)d_in[0];
    const float* w1  = (const float*)d_in[1];
    const float* w2  = (const float*)d_in[2];
    const float* tw  = (const float*)d_in[3];
    const int*   ids = (const int*)d_in[4];
    float* out = (float*)d_out;

    const int SMB = 61440;
    cudaFuncSetAttribute(k_gemm<HID, 1, 0>,
                         cudaFuncAttributeMaxDynamicSharedMemorySize, SMB);
    cudaFuncSetAttribute(k_gemm<FF, 0, 1>,
                         cudaFuncAttributeMaxDynamicSharedMemorySize, SMB);

    k_setup<<<1, 256>>>(ids);
    k_hist<<<(NA + 255) / 256, 256>>>(ids);
    k_scan<<<1, 1>>>();
    k_fill<<<(NA + 255) / 256, 256>>>(ids);
    k_gemm<HID, 1, 0><<<dim3(GUN / 128, NEXP), 512, SMB>>>(x, w1);
    k_act<<<4096, 256>>>();
    k_gemm<FF, 0, 1><<<dim3(HID / 128, NEXP), 512, SMB>>>(x, w2);
    k_combine<<<T_TOK, 256>>>(tw, out);
}

// round 4
// speedup vs baseline: 3.9634x; 1.0581x over previous
#include <cuda_runtime.h>

// ---------------------------------------------------------------------------
// Fused MoE via grouped fp16 mma.sync (m16n8k16) GEMMs, fp32 accumulate.
//   T=1024, H=2048, F=1408, E=32, K=6.
// setup -> hist -> scan -> fill -> GEMM1 -> swiglu -> GEMM2 -> combine
// ---------------------------------------------------------------------------

#define T_TOK 1024
#define HID   2048
#define FF    1408
#define NEXP  32
#define TOPK  6
#define NA    (T_TOK * TOPK)    // 6144
#define GUN   (2 * FF)          // 2816

typedef unsigned int u32;

// smem: A 3 stages x 256 rows x 40 floats; B 3 stages x 128 rows x 40 floats
#define ASTRIDEF 40u
#define AST   40960u
#define BBASE 122880u
#define BST   20480u
#define SMB   184320

// ---------------- device scratch -------------------------------------------
__device__ int   d_count[NEXP];
__device__ int   d_off[NEXP];
__device__ int   d_fill[NEXP];
__device__ int   d_flag;
__device__ int   d_tok[NA];
__device__ int   d_inv[NA];
__device__ float d_G [(size_t)NA * GUN];
__device__ float d_Hb[(size_t)NA * FF];
__device__ float d_Y [(size_t)NA * HID];

// ---------------- PTX helpers ----------------------------------------------
__device__ __forceinline__ u32 smem_u32(const void* p) {
    u32 a;
    asm("{ .reg .u64 t; cvta.to.shared.u64 t, %1; cvt.u32.u64 %0, t; }"
        : "=r"(a) : "l"(p));
    return a;
}
__device__ __forceinline__ u32 pack2h(float2 v) {   // {lo=v.x, hi=v.y} fp16x2
    u32 r;
    asm("cvt.rn.f16x2.f32 %0, %1, %2;" : "=r"(r) : "f"(v.y), "f"(v.x));
    return r;
}
#define CP16(dst, src, sz) \
    asm volatile("cp.async.cg.shared.global [%0], [%1], 16, %2;" \
                 :: "r"(dst), "l"(src), "r"(sz))
#define CP_COMMIT() asm volatile("cp.async.commit_group;" ::: "memory")
#define CP_WAIT(n)  asm volatile("cp.async.wait_group %0;" :: "n"(n) : "memory")

__device__ __forceinline__ void mma16(float* d, u32 a0, u32 a1, u32 a2, u32 a3,
                                      u32 b0, u32 b1) {
    asm volatile(
        "mma.sync.aligned.m16n8k16.row.col.f32.f16.f16.f32 "
        "{%0,%1,%2,%3}, {%4,%5,%6,%7}, {%8,%9}, {%0,%1,%2,%3};"
        : "+f"(d[0]), "+f"(d[1]), "+f"(d[2]), "+f"(d[3])
        : "r"(a0), "r"(a1), "r"(a2), "r"(a3), "r"(b0), "r"(b1));
}

// ---------------- routing prep ---------------------------------------------
__global__ void k_setup(const int* __restrict__ ids32) {
    __shared__ int f;
    int tid = threadIdx.x;
    if (tid < NEXP) d_count[tid] = 0;
    if (tid == 0) f = 0;
    __syncthreads();
    int local = 0;
    for (int i = tid; i < NA / 2; i += blockDim.x)
        if (ids32[2 * i + 1] != 0) local = 1;
    if (local) f = 1;
    __syncthreads();
    if (tid == 0) d_flag = f;
}
__device__ __forceinline__ int get_id(const int* ids32, int i, int flag) {
    return flag ? ids32[i] : ids32[2 * i];
}
__global__ void k_hist(const int* __restrict__ ids32) {
    int i = blockIdx.x * blockDim.x + threadIdx.x;
    if (i >= NA) return;
    atomicAdd(&d_count[get_id(ids32, i, d_flag)], 1);
}
__global__ void k_scan() {
    int off = 0;
    for (int e = 0; e < NEXP; e++) {
        d_off[e] = off; d_fill[e] = off; off += d_count[e];
    }
}
__global__ void k_fill(const int* __restrict__ ids32) {
    int i = blockIdx.x * blockDim.x + threadIdx.x;
    if (i >= NA) return;
    int e = get_id(ids32, i, d_flag);
    int pos = atomicAdd(&d_fill[e], 1);
    d_tok[pos] = i / TOPK;
    d_inv[i] = pos;
}

// ---------------- grouped fp16 GEMM ----------------------------------------
// BM=256, BN=128, BK=32, 256 threads (8 warps, warp tile 64x64).
// 3-stage cp.async pipeline, one barrier per k-iter.
template<int KDIM, int GATHER, int OUTSEL>
__global__ __launch_bounds__(256, 1) void k_gemm(const float* __restrict__ Ain,
                                                 const float* __restrict__ Bw) {
    constexpr int NIT = KDIM / 32;
    extern __shared__ char smem[];
    const int e = blockIdx.y;
    const int cnt = d_count[e];
    if (cnt == 0) return;
    const int row0e = d_off[e];
    const int n0 = blockIdx.x * 128;
    const long long bStride = (OUTSEL == 0) ? (long long)GUN * HID
                                            : (long long)HID * FF;
    float* Cb = (OUTSEL == 0) ? d_G : d_Y;
    const int ldc = (OUTSEL == 0) ? GUN : HID;
    const float* A = GATHER ? Ain : d_Hb;

    const int tid = threadIdx.x;
    const int wid = tid >> 5, lane = tid & 31;
    const int r4 = lane >> 2, c4 = lane & 3;
    const int warpM = (wid & 3) * 64;
    const int warpN = (wid >> 2) * 64;
    const u32 sb = smem_u32(smem);

    // loader geometry: chunk = 16B slot in 128B row, rb = row within pass
    const int chunk = tid & 7, rb = tid >> 3;
    const float* bS[4];
    u32 bD[4];
#pragma unroll
    for (int p = 0; p < 4; p++) {
        int row = rb + 32 * p;
        bS[p] = Bw + (long long)e * bStride + (long long)(n0 + row) * KDIM
                   + chunk * 4;
        bD[p] = sb + BBASE + (u32)row * 160u + (u32)chunk * 16u;
    }

    for (int m0 = 0; m0 < cnt; m0 += 256) {
        const float* aS[8];
        u32 aV[8], aD[8];
#pragma unroll
        for (int j = 0; j < 8; j++) {
            int r = rb + 32 * j;
            int valid = (m0 + r) < cnt;
            long long src = 0;
            if (valid)
                src = GATHER ? (long long)d_tok[row0e + m0 + r]
                             : (long long)(row0e + m0 + r);
            aS[j] = A + src * KDIM + chunk * 4;
            aV[j] = valid ? 16u : 0u;
            aD[j] = sb + (u32)r * 160u + (u32)chunk * 16u;
        }
        const int rem = cnt - m0 - warpM;
        const int mtMax = rem >= 64 ? 4 : (rem > 0 ? ((rem + 15) >> 4) : 0);

        float acc[4][8][4];
#pragma unroll
        for (int mt = 0; mt < 4; mt++)
#pragma unroll
            for (int nt = 0; nt < 8; nt++)
#pragma unroll
                for (int q = 0; q < 4; q++) acc[mt][nt][q] = 0.f;

#define ISSUE(s, k0) do {                                                  \
        u32 _ao = (u32)(s) * AST;                                          \
        u32 _bo = (u32)(s) * BST;                                          \
        _Pragma("unroll")                                                  \
        for (int _j = 0; _j < 8; _j++)                                     \
            CP16(aD[_j] + _ao, aS[_j] + (k0), aV[_j]);                     \
        _Pragma("unroll")                                                  \
        for (int _p = 0; _p < 4; _p++)                                     \
            CP16(bD[_p] + _bo, bS[_p] + (k0), 16u);                        \
    } while (0)

        ISSUE(0, 0);  CP_COMMIT();
        ISSUE(1, 32); CP_COMMIT();

        for (int it = 0; it < NIT; it++) {
            const int buf = it % 3;
            CP_WAIT(1);
            __syncthreads();
            const int ns = it + 2;
            if (ns < NIT) ISSUE(ns % 3, ns * 32);
            CP_COMMIT();                       // empty group ok near the tail

            const float* Af = (const float*)(smem + buf * AST);
            const float* Bf = (const float*)(smem + BBASE + buf * BST);
#pragma unroll
            for (int ks = 0; ks < 2; ks++) {
                u32 b[8][2];
#pragma unroll
                for (int nt = 0; nt < 8; nt++) {
                    int cb = (warpN + nt * 8 + r4) * 40 + ks * 16 + 2 * c4;
                    b[nt][0] = pack2h(*(const float2*)&Bf[cb]);
                    b[nt][1] = pack2h(*(const float2*)&Bf[cb + 8]);
                }
#pragma unroll
                for (int mt = 0; mt < 4; mt++) {
                    if (mt < mtMax) {
                        int ab = (warpM + mt * 16 + r4) * 40 + ks * 16 + 2 * c4;
                        u32 a0 = pack2h(*(const float2*)&Af[ab]);
                        u32 a1 = pack2h(*(const float2*)&Af[ab + 320]);
                        u32 a2 = pack2h(*(const float2*)&Af[ab + 8]);
                        u32 a3 = pack2h(*(const float2*)&Af[ab + 328]);
#pragma unroll
                        for (int nt = 0; nt < 8; nt++)
                            mma16(acc[mt][nt], a0, a1, a2, a3,
                                  b[nt][0], b[nt][1]);
                    }
                }
            }
        }
        CP_WAIT(0);

        // epilogue
#pragma unroll
        for (int mt = 0; mt < 4; mt++) {
            int rloc = m0 + warpM + mt * 16 + r4;
#pragma unroll
            for (int nt = 0; nt < 8; nt++) {
                int col = n0 + warpN + nt * 8 + c4 * 2;
                if (rloc < cnt) {
                    float2 v = make_float2(acc[mt][nt][0], acc[mt][nt][1]);
                    *(float2*)&Cb[(long long)(row0e + rloc) * ldc + col] = v;
                }
                if (rloc + 8 < cnt) {
                    float2 v = make_float2(acc[mt][nt][2], acc[mt][nt][3]);
                    *(float2*)&Cb[(long long)(row0e + rloc + 8) * ldc + col] = v;
                }
            }
        }
        __syncthreads();
#undef ISSUE
    }
}

// ---------------- SwiGLU ----------------------------------------------------
__global__ void k_act() {
    const long long total = (long long)NA * FF;
    for (long long i = blockIdx.x * (long long)blockDim.x + threadIdx.x;
         i < total; i += (long long)gridDim.x * blockDim.x) {
        int p = (int)(i / FF), f = (int)(i % FF);
        float gv = d_G[(long long)p * GUN + f];
        float uv = d_G[(long long)p * GUN + FF + f];
        float s = 1.f / (1.f + __expf(-gv));
        d_Hb[i] = gv * s * uv;
    }
}

// ---------------- combine ---------------------------------------------------
__global__ void k_combine(const float* __restrict__ tw, float* __restrict__ out) {
    int t = blockIdx.x;
    __shared__ int pos[TOPK];
    __shared__ float wv[TOPK];
    if (threadIdx.x < TOPK) {
        pos[threadIdx.x] = d_inv[t * TOPK + threadIdx.x];
        wv[threadIdx.x]  = tw[t * TOPK + threadIdx.x];
    }
    __syncthreads();
    for (int h = threadIdx.x * 4; h < HID; h += blockDim.x * 4) {
        float4 acc = make_float4(0.f, 0.f, 0.f, 0.f);
#pragma unroll
        for (int k = 0; k < TOPK; k++) {
            float4 v = *(const float4*)(d_Y + (size_t)pos[k] * HID + h);
            acc.x += wv[k] * v.x; acc.y += wv[k] * v.y;
            acc.z += wv[k] * v.z; acc.w += wv[k] * v.w;
        }
        *(float4*)(out + (size_t)t * HID + h) = acc;
    }
}

// ---------------- launch ----------------------------------------------------
extern "C" void kernel_launch(void* const* d_in, const int* in_sizes, int n_in,
                              void* d_out, int out_size) {
    const float* x   = (const float*)d_in[0];
    const float* w1  = (const float*)d_in[1];
    const float* w2  = (const float*)d_in[2];
    const float* tw  = (const float*)d_in[3];
    const int*   ids = (const int*)d_in[4];
    float* out = (float*)d_out;

    cudaFuncSetAttribute(k_gemm<HID, 1, 0>,
                         cudaFuncAttributeMaxDynamicSharedMemorySize, SMB);
    cudaFuncSetAttribute(k_gemm<FF, 0, 1>,
                         cudaFuncAttributeMaxDynamicSharedMemorySize, SMB);

    k_setup<<<1, 256>>>(ids);
    k_hist<<<(NA + 255) / 256, 256>>>(ids);
    k_scan<<<1, 1>>>();
    k_fill<<<(NA + 255) / 256, 256>>>(ids);
    k_gemm<HID, 1, 0><<<dim3(GUN / 128, NEXP), 256, SMB>>>(x, w1);
    k_act<<<4096, 256>>>();
    k_gemm<FF, 0, 1><<<dim3(HID / 128, NEXP), 256, SMB>>>(x, w2);
    k_combine<<<T_TOK, 256>>>(tw, out);
}

// round 5
// speedup vs baseline: 6.4148x; 1.6185x over previous
#include <cuda_runtime.h>

// ---------------------------------------------------------------------------
// Fused MoE via grouped fp16 mma.sync (m16n8k16) GEMMs, fp32 accumulate.
//   T=1024, H=2048, F=1408, E=32, K=6.
// setup -> hist -> scan -> fill -> GEMM1 -> swiglu -> GEMM2(+weighted
// scatter into out) .  M-stripes interleaved across SMSPs at 16-row grain so
// expert-count padding idles no sub-partition.
// ---------------------------------------------------------------------------

#define T_TOK 1024
#define HID   2048
#define FF    1408
#define NEXP  32
#define TOPK  6
#define NA    (T_TOK * TOPK)    // 6144
#define GUN   (2 * FF)          // 2816

typedef unsigned int u32;

// smem: A 3 stages x 256 rows x 40 floats; B 3 stages x 128 rows x 40 floats
#define AST   40960u
#define BBASE 122880u
#define BST   20480u
#define SMB   184320

// ---------------- device scratch -------------------------------------------
__device__ int   d_count[NEXP];
__device__ int   d_off[NEXP];
__device__ int   d_fill[NEXP];
__device__ int   d_flag;
__device__ int   d_tok[NA];
__device__ float d_wts[NA];
__device__ float d_G [(size_t)NA * GUN];
__device__ float d_Hb[(size_t)NA * FF];

// ---------------- PTX helpers ----------------------------------------------
__device__ __forceinline__ u32 smem_u32(const void* p) {
    u32 a;
    asm("{ .reg .u64 t; cvta.to.shared.u64 t, %1; cvt.u32.u64 %0, t; }"
        : "=r"(a) : "l"(p));
    return a;
}
__device__ __forceinline__ u32 pack2h(float2 v) {   // {lo=v.x, hi=v.y} fp16x2
    u32 r;
    asm("cvt.rn.f16x2.f32 %0, %1, %2;" : "=r"(r) : "f"(v.y), "f"(v.x));
    return r;
}
#define CP16(dst, src, sz) \
    asm volatile("cp.async.cg.shared.global [%0], [%1], 16, %2;" \
                 :: "r"(dst), "l"(src), "r"(sz))
#define CP_COMMIT() asm volatile("cp.async.commit_group;" ::: "memory")
#define CP_WAIT(n)  asm volatile("cp.async.wait_group %0;" :: "n"(n) : "memory")

__device__ __forceinline__ void mma16(float* d, u32 a0, u32 a1, u32 a2, u32 a3,
                                      u32 b0, u32 b1) {
    asm volatile(
        "mma.sync.aligned.m16n8k16.row.col.f32.f16.f16.f32 "
        "{%0,%1,%2,%3}, {%4,%5,%6,%7}, {%8,%9}, {%0,%1,%2,%3};"
        : "+f"(d[0]), "+f"(d[1]), "+f"(d[2]), "+f"(d[3])
        : "r"(a0), "r"(a1), "r"(a2), "r"(a3), "r"(b0), "r"(b1));
}

// ---------------- routing prep ---------------------------------------------
__global__ void k_zero_out(float4* out) {
    out[blockIdx.x * blockDim.x + threadIdx.x] = make_float4(0.f, 0.f, 0.f, 0.f);
}
__global__ void k_setup(const int* __restrict__ ids32) {
    __shared__ int f;
    int tid = threadIdx.x;
    if (tid < NEXP) d_count[tid] = 0;
    if (tid == 0) f = 0;
    __syncthreads();
    int local = 0;
    for (int i = tid; i < NA / 2; i += blockDim.x)
        if (ids32[2 * i + 1] != 0) local = 1;
    if (local) f = 1;
    __syncthreads();
    if (tid == 0) d_flag = f;
}
__device__ __forceinline__ int get_id(const int* ids32, int i, int flag) {
    return flag ? ids32[i] : ids32[2 * i];
}
__global__ void k_hist(const int* __restrict__ ids32) {
    int i = blockIdx.x * blockDim.x + threadIdx.x;
    if (i >= NA) return;
    atomicAdd(&d_count[get_id(ids32, i, d_flag)], 1);
}
__global__ void k_scan() {
    int off = 0;
    for (int e = 0; e < NEXP; e++) {
        d_off[e] = off; d_fill[e] = off; off += d_count[e];
    }
}
__global__ void k_fill(const int* __restrict__ ids32,
                       const float* __restrict__ tw) {
    int i = blockIdx.x * blockDim.x + threadIdx.x;
    if (i >= NA) return;
    int e = get_id(ids32, i, d_flag);
    int pos = atomicAdd(&d_fill[e], 1);
    d_tok[pos] = i / TOPK;
    d_wts[pos] = tw[i];
}

// ---------------- grouped fp16 GEMM ----------------------------------------
// BM=256, BN=128, BK=32, 256 threads (8 warps).  Warp covers four 16-row
// stripes at rows (wid&3)*16 + mt*64 (mt=0..3) x 64 cols -> padding rows
// cluster into stripes every SMSP can skip via mtMax.
// OUTSEL 0: C=d_G.  OUTSEL 1: weighted atomic scatter into Out.
template<int KDIM, int GATHER, int OUTSEL>
__global__ __launch_bounds__(256, 1) void k_gemm(const float* __restrict__ Ain,
                                                 const float* __restrict__ Bw,
                                                 float* __restrict__ Out) {
    constexpr int NIT = KDIM / 32;
    extern __shared__ char smem[];
    const int e = blockIdx.y;
    const int cnt = d_count[e];
    if (cnt == 0) return;
    const int row0e = d_off[e];
    const int n0 = blockIdx.x * 128;
    const long long bStride = (OUTSEL == 0) ? (long long)GUN * HID
                                            : (long long)HID * FF;
    const float* A = GATHER ? Ain : d_Hb;

    const int tid = threadIdx.x;
    const int wid = tid >> 5, lane = tid & 31;
    const int r4 = lane >> 2, c4 = lane & 3;
    const int s16   = (wid & 3) * 16;       // SMSP-interleaved M base
    const int warpN = (wid >> 2) * 64;
    const u32 sb = smem_u32(smem);

    const int chunk = tid & 7, rb = tid >> 3;
    const float* bS[4];
    u32 bD[4];
#pragma unroll
    for (int p = 0; p < 4; p++) {
        int row = rb + 32 * p;
        bS[p] = Bw + (long long)e * bStride + (long long)(n0 + row) * KDIM
                   + chunk * 4;
        bD[p] = sb + BBASE + (u32)row * 160u + (u32)chunk * 16u;
    }

    for (int m0 = 0; m0 < cnt; m0 += 256) {
        const float* aS[8];
        u32 aV[8], aD[8];
#pragma unroll
        for (int j = 0; j < 8; j++) {
            int r = rb + 32 * j;
            int valid = (m0 + r) < cnt;
            long long src = 0;
            if (valid)
                src = GATHER ? (long long)d_tok[row0e + m0 + r]
                             : (long long)(row0e + m0 + r);
            aS[j] = A + src * KDIM + chunk * 4;
            aV[j] = valid ? 16u : 0u;
            aD[j] = sb + (u32)r * 160u + (u32)chunk * 16u;
        }
        const int rem = cnt - m0;
        const int tv = rem - s16;
        const int mtMax = (tv <= 0) ? 0 : ((tv + 63) >> 6 > 4 ? 4 : (tv + 63) >> 6);

        float acc[4][8][4];
#pragma unroll
        for (int mt = 0; mt < 4; mt++)
#pragma unroll
            for (int nt = 0; nt < 8; nt++)
#pragma unroll
                for (int q = 0; q < 4; q++) acc[mt][nt][q] = 0.f;

#define ISSUE(s, k0) do {                                                  \
        u32 _ao = (u32)(s) * AST;                                          \
        u32 _bo = (u32)(s) * BST;                                          \
        _Pragma("unroll")                                                  \
        for (int _j = 0; _j < 8; _j++)                                     \
            CP16(aD[_j] + _ao, aS[_j] + (k0), aV[_j]);                     \
        _Pragma("unroll")                                                  \
        for (int _p = 0; _p < 4; _p++)                                     \
            CP16(bD[_p] + _bo, bS[_p] + (k0), 16u);                        \
    } while (0)

        ISSUE(0, 0);  CP_COMMIT();
        ISSUE(1, 32); CP_COMMIT();

        for (int it = 0; it < NIT; it++) {
            const int buf = it % 3;
            CP_WAIT(1);
            __syncthreads();
            const int ns = it + 2;
            if (ns < NIT) ISSUE(ns % 3, ns * 32);
            CP_COMMIT();

            const float* Af = (const float*)(smem + buf * AST);
            const float* Bf = (const float*)(smem + BBASE + buf * BST);
#pragma unroll
            for (int ks = 0; ks < 2; ks++) {
                u32 b[8][2];
#pragma unroll
                for (int nt = 0; nt < 8; nt++) {
                    int cb = (warpN + nt * 8 + r4) * 40 + ks * 16 + 2 * c4;
                    b[nt][0] = pack2h(*(const float2*)&Bf[cb]);
                    b[nt][1] = pack2h(*(const float2*)&Bf[cb + 8]);
                }
#pragma unroll
                for (int mt = 0; mt < 4; mt++) {
                    if (mt < mtMax) {
                        int ab = (s16 + mt * 64 + r4) * 40 + ks * 16 + 2 * c4;
                        u32 a0 = pack2h(*(const float2*)&Af[ab]);
                        u32 a1 = pack2h(*(const float2*)&Af[ab + 320]);
                        u32 a2 = pack2h(*(const float2*)&Af[ab + 8]);
                        u32 a3 = pack2h(*(const float2*)&Af[ab + 328]);
#pragma unroll
                        for (int nt = 0; nt < 8; nt++)
                            mma16(acc[mt][nt], a0, a1, a2, a3,
                                  b[nt][0], b[nt][1]);
                    }
                }
            }
        }
        CP_WAIT(0);

        // epilogue
#pragma unroll
        for (int mt = 0; mt < 4; mt++) {
            int rloc = m0 + s16 + mt * 64 + r4;
            if (OUTSEL == 0) {
#pragma unroll
                for (int nt = 0; nt < 8; nt++) {
                    int col = n0 + warpN + nt * 8 + c4 * 2;
                    if (rloc < cnt) {
                        float2 v = make_float2(acc[mt][nt][0], acc[mt][nt][1]);
                        *(float2*)&d_G[(long long)(row0e + rloc) * GUN + col] = v;
                    }
                    if (rloc + 8 < cnt) {
                        float2 v = make_float2(acc[mt][nt][2], acc[mt][nt][3]);
                        *(float2*)&d_G[(long long)(row0e + rloc + 8) * GUN + col] = v;
                    }
                }
            } else {
                int v0 = rloc < cnt, v1 = (rloc + 8) < cnt;
                int t0 = 0, t1 = 0; float w0 = 0.f, w1 = 0.f;
                if (v0) { t0 = d_tok[row0e + rloc];     w0 = d_wts[row0e + rloc]; }
                if (v1) { t1 = d_tok[row0e + rloc + 8]; w1 = d_wts[row0e + rloc + 8]; }
#pragma unroll
                for (int nt = 0; nt < 8; nt++) {
                    int col = n0 + warpN + nt * 8 + c4 * 2;
                    if (v0) {
                        float* o = Out + (long long)t0 * HID + col;
                        atomicAdd(o,     w0 * acc[mt][nt][0]);
                        atomicAdd(o + 1, w0 * acc[mt][nt][1]);
                    }
                    if (v1) {
                        float* o = Out + (long long)t1 * HID + col;
                        atomicAdd(o,     w1 * acc[mt][nt][2]);
                        atomicAdd(o + 1, w1 * acc[mt][nt][3]);
                    }
                }
            }
        }
        __syncthreads();
#undef ISSUE
    }
}

// ---------------- SwiGLU ----------------------------------------------------
__global__ void k_act() {
    const long long total = (long long)NA * FF;
    for (long long i = blockIdx.x * (long long)blockDim.x + threadIdx.x;
         i < total; i += (long long)gridDim.x * blockDim.x) {
        int p = (int)(i / FF), f = (int)(i % FF);
        float gv = d_G[(long long)p * GUN + f];
        float uv = d_G[(long long)p * GUN + FF + f];
        float s = 1.f / (1.f + __expf(-gv));
        d_Hb[i] = gv * s * uv;
    }
}

// ---------------- launch ----------------------------------------------------
extern "C" void kernel_launch(void* const* d_in, const int* in_sizes, int n_in,
                              void* d_out, int out_size) {
    const float* x   = (const float*)d_in[0];
    const float* w1  = (const float*)d_in[1];
    const float* w2  = (const float*)d_in[2];
    const float* tw  = (const float*)d_in[3];
    const int*   ids = (const int*)d_in[4];
    float* out = (float*)d_out;

    cudaFuncSetAttribute(k_gemm<HID, 1, 0>,
                         cudaFuncAttributeMaxDynamicSharedMemorySize, SMB);
    cudaFuncSetAttribute(k_gemm<FF, 0, 1>,
                         cudaFuncAttributeMaxDynamicSharedMemorySize, SMB);

    k_zero_out<<<1024, 512>>>((float4*)out);
    k_setup<<<1, 256>>>(ids);
    k_hist<<<(NA + 255) / 256, 256>>>(ids);
    k_scan<<<1, 1>>>();
    k_fill<<<(NA + 255) / 256, 256>>>(ids, tw);
    k_gemm<HID, 1, 0><<<dim3(GUN / 128, NEXP), 256, SMB>>>(x, w1, nullptr);
    k_act<<<4096, 256>>>();
    k_gemm<FF, 0, 1><<<dim3(HID / 128, NEXP), 256, SMB>>>(x, w2, out);
}